// round 15
// baseline (speedup 1.0000x reference)
#include <cuda_runtime.h>
#include <cuda_fp16.h>
#include <cstdint>

#define N_PTS   32768
#define DIM     256
#define KCODES  1024
#define DECAYF  0.99f
#define OMDECAY 0.01f
#define EPSF    1e-5f
#define MARGIN  6.0f
#define CMAX    32

// Output layout (concatenated, float32)
#define OFF_ZQ    0
#define OFF_LOSS  (N_PTS * DIM)
#define OFF_IDX   (OFF_LOSS + 1)
#define OFF_EMB   (OFF_IDX + N_PTS)
#define OFF_CS    (OFF_EMB + KCODES * DIM)
#define OFF_EMAW  (OFF_CS + KCODES)

__device__ float    g_enorm[KCODES];
__device__ float    g_loss;
__device__ float    g_n;
__device__ unsigned g_maxz_bits;
__device__ unsigned g_maxe_bits;
__device__ int8_t   g_z8[N_PTS * DIM];
__device__ int8_t   g_e8[KCODES * DIM];
__device__ __half   g_dist[N_PTS * KCODES];
__device__ int      g_sel[N_PTS];
__device__ int      g_cnt[KCODES];
__device__ int      g_off[KCODES];
__device__ int      g_fill[KCODES];
__device__ int      g_bkt[N_PTS];

// ---------------------------------------------------------------------------
// helpers
// ---------------------------------------------------------------------------
__device__ __forceinline__ uint32_t smem_u32(const void* p) {
    uint32_t a;
    asm("{ .reg .u64 t; cvta.to.shared.u64 t, %1; cvt.u32.u64 %0, t; }"
        : "=r"(a) : "l"(p));
    return a;
}
__device__ __forceinline__ void cp16(uint32_t dst, const void* src) {
    asm volatile("cp.async.cg.shared.global [%0], [%1], 16;"
                 :: "r"(dst), "l"(__cvta_generic_to_global(src)) : "memory");
}
#define CP_COMMIT() asm volatile("cp.async.commit_group;" ::: "memory")
#define CP_WAIT0()  asm volatile("cp.async.wait_group 0;" ::: "memory")

#define LDSM_X4(r0, r1, r2, r3, a) \
    asm volatile("ldmatrix.sync.aligned.m8n8.x4.shared.b16 {%0,%1,%2,%3}, [%4];" \
                 : "=r"(r0), "=r"(r1), "=r"(r2), "=r"(r3) : "r"(a))
#define LDSM_X2(r0, r1, a) \
    asm volatile("ldmatrix.sync.aligned.m8n8.x2.shared.b16 {%0,%1}, [%2];" \
                 : "=r"(r0), "=r"(r1) : "r"(a))

__device__ __forceinline__ void imma16832(int* c, const uint32_t* a, const uint32_t* b) {
    asm volatile("mma.sync.aligned.m16n8k32.row.col.s32.s8.s8.s32 "
                 "{%0,%1,%2,%3}, {%4,%5,%6,%7}, {%8,%9}, {%0,%1,%2,%3};"
                 : "+r"(c[0]), "+r"(c[1]), "+r"(c[2]), "+r"(c[3])
                 : "r"(a[0]), "r"(a[1]), "r"(a[2]), "r"(a[3]), "r"(b[0]), "r"(b[1]));
}

// ---------------------------------------------------------------------------
// k_zero: reset run-state scalars
// ---------------------------------------------------------------------------
__global__ void k_zero() {
    if (threadIdx.x == 0) { g_maxz_bits = 0; g_maxe_bits = 0; g_loss = 0.0f; }
}

// ---------------------------------------------------------------------------
// k_maxabs: global max|z|, max|e| (positive-float bits compare as uint)
// ---------------------------------------------------------------------------
__global__ void k_maxabs(const float* __restrict__ z, const float* __restrict__ e) {
    int tid = blockIdx.x * blockDim.x + threadIdx.x;   // 2048*256 = 524288
    const float4* zp = (const float4*)z;
    float mz = 0.0f, me = 0.0f;
#pragma unroll
    for (int i = 0; i < 4; i++) {
        float4 v = zp[tid + i * 524288];
        mz = fmaxf(mz, fmaxf(fmaxf(fabsf(v.x), fabsf(v.y)),
                             fmaxf(fabsf(v.z), fabsf(v.w))));
    }
    if (tid < KCODES * DIM / 4) {
        float4 v = ((const float4*)e)[tid];
        me = fmaxf(fabsf(v.x), fmaxf(fabsf(v.y), fmaxf(fabsf(v.z), fabsf(v.w))));
    }
#pragma unroll
    for (int off = 16; off; off >>= 1) {
        mz = fmaxf(mz, __shfl_xor_sync(0xFFFFFFFFu, mz, off));
        me = fmaxf(me, __shfl_xor_sync(0xFFFFFFFFu, me, off));
    }
    if ((threadIdx.x & 31) == 0) {
        atomicMax(&g_maxz_bits, __float_as_uint(mz));
        atomicMax(&g_maxe_bits, __float_as_uint(me));
    }
}

// ---------------------------------------------------------------------------
// k_prep: int8 quantize z, e with measured global scales; zero counters
// ---------------------------------------------------------------------------
__global__ void k_prep(const float* __restrict__ z, const float* __restrict__ e) {
    int idx = blockIdx.x * blockDim.x + threadIdx.x;   // covers N*D/4 = 2097152
    float rz = 127.0f / __uint_as_float(g_maxz_bits);
    float re = 127.0f / __uint_as_float(g_maxe_bits);
    int i4 = idx * 4;
    float4 v = *(const float4*)(z + i4);
    char4 q;
    q.x = (char)__float2int_rn(v.x * rz);
    q.y = (char)__float2int_rn(v.y * rz);
    q.z = (char)__float2int_rn(v.z * rz);
    q.w = (char)__float2int_rn(v.w * rz);
    *(char4*)(g_z8 + i4) = q;
    if (i4 < KCODES * DIM) {
        float4 w = *(const float4*)(e + i4);
        char4 p;
        p.x = (char)__float2int_rn(w.x * re);
        p.y = (char)__float2int_rn(w.y * re);
        p.z = (char)__float2int_rn(w.z * re);
        p.w = (char)__float2int_rn(w.w * re);
        *(char4*)(g_e8 + i4) = p;
    }
    if (idx < KCODES) { g_cnt[idx] = 0; g_fill[idx] = 0; }
}

__global__ void k_norm(const float* __restrict__ emb) {
    int warp = (blockIdx.x * blockDim.x + threadIdx.x) >> 5;
    int lane = threadIdx.x & 31;
    if (warp >= KCODES) return;
    const float4* row = (const float4*)(emb + (size_t)warp * DIM);
    float4 a = row[lane * 2 + 0];
    float4 b = row[lane * 2 + 1];
    float s = a.x*a.x + a.y*a.y + a.z*a.z + a.w*a.w
            + b.x*b.x + b.y*b.y + b.z*b.z + b.w*b.w;
#pragma unroll
    for (int off = 16; off; off >>= 1) s += __shfl_down_sync(0xFFFFFFFFu, s, off);
    if (lane == 0) g_enorm[warp] = s;
}

// ---------------------------------------------------------------------------
// int8 IMMA distance GEMM: 128x128 tile, full K=256 bytes resident in SMEM.
// dist = ||e||^2 - 2 * s2 * (z8 . e8), fp16 out. Same fragment addressing
// as the proven fp16 kernel (byte-identical ldmatrix layout for s8 k32).
// ---------------------------------------------------------------------------
#define ROWB    272                          // 256 B + 16 pad (16 mod 128 -> conflict-free)
#define A_OFF   0
#define B_OFF   (128 * ROWB)                 // 34816
#define EN_OFF  (2 * 128 * ROWB)             // 69632
#define SMEM_SZ (EN_OFF + 512)               // 70144

__global__ __launch_bounds__(256, 2) void k_dist_imma() {
    extern __shared__ char smem[];
    uint32_t sb = smem_u32(smem);
    int tid = threadIdx.x;
    int wid = tid >> 5;
    int lane = tid & 31;
    int n0 = blockIdx.x * 128;
    int m0 = blockIdx.y * 128;
    int warp_m = wid & 1;
    int warp_n = wid >> 1;

    // load A (z tile) + B (e tile): 128 rows x 256B each = 2048 chunks each
#pragma unroll
    for (int i = 0; i < 8; i++) {
        int ch = tid + i * 256;
        int r = ch >> 4, sg = ch & 15;
        cp16(sb + A_OFF + r * ROWB + sg * 16, g_z8 + (size_t)(m0 + r) * DIM + sg * 16);
        cp16(sb + B_OFF + r * ROWB + sg * 16, g_e8 + (size_t)(n0 + r) * DIM + sg * 16);
    }
    CP_COMMIT();
    if (tid < 128) ((float*)(smem + EN_OFF))[tid] = g_enorm[n0 + tid];
    CP_WAIT0();
    __syncthreads();

    int acc[4][4][4] = {};

    int rA   = warp_m * 64 + (lane & 7) + (((lane >> 3) & 1) << 3);
    int cA16 = ((lane >> 4) & 1) << 4;       // byte offset
    int rB   = warp_n * 32 + (lane & 7);
    int cB16 = ((lane >> 3) & 1) << 4;

#pragma unroll
    for (int ks = 0; ks < 8; ks++) {         // k32 int8 per step
        int kb = ks * 32;
        uint32_t a[4][4], b[4][2];
#pragma unroll
        for (int mi = 0; mi < 4; mi++) {
            uint32_t ad = sb + A_OFF + (rA + mi * 16) * ROWB + kb + cA16;
            LDSM_X4(a[mi][0], a[mi][1], a[mi][2], a[mi][3], ad);
        }
#pragma unroll
        for (int nj = 0; nj < 4; nj++) {
            uint32_t bd = sb + B_OFF + (rB + nj * 8) * ROWB + kb + cB16;
            LDSM_X2(b[nj][0], b[nj][1], bd);
        }
#pragma unroll
        for (int mi = 0; mi < 4; mi++)
#pragma unroll
            for (int nj = 0; nj < 4; nj++)
                imma16832(acc[mi][nj], a[mi], b[nj]);
    }

    float sz = __uint_as_float(g_maxz_bits) * (1.0f / 127.0f);
    float se = __uint_as_float(g_maxe_bits) * (1.0f / 127.0f);
    float s2 = 2.0f * sz * se;

    const float* en = (const float*)(smem + EN_OFF);
#pragma unroll
    for (int mi = 0; mi < 4; mi++) {
#pragma unroll
        for (int nj = 0; nj < 4; nj++) {
            int cw = warp_n * 32 + nj * 8 + (lane & 3) * 2;
            int r0 = m0 + warp_m * 64 + mi * 16 + (lane >> 2);
            float e0 = en[cw], e1 = en[cw + 1];
            __half2 v0 = __floats2half2_rn(e0 - s2 * (float)acc[mi][nj][0],
                                           e1 - s2 * (float)acc[mi][nj][1]);
            __half2 v1 = __floats2half2_rn(e0 - s2 * (float)acc[mi][nj][2],
                                           e1 - s2 * (float)acc[mi][nj][3]);
            *(__half2*)(g_dist + (size_t)r0 * KCODES + n0 + cw) = v0;
            *(__half2*)(g_dist + (size_t)(r0 + 8) * KCODES + n0 + cw) = v1;
        }
    }
}

// ---------------------------------------------------------------------------
// k_selgather: warp per point. Full-row approx min -> margin candidates ->
// exact fp32 rescore -> fused gather (z_q, idx, loss, counts).
// ---------------------------------------------------------------------------
__global__ __launch_bounds__(256) void k_selgather(const float* __restrict__ z,
                                                   const float* __restrict__ emb,
                                                   float* __restrict__ out) {
    __shared__ int s_cnt[8];
    __shared__ int s_list[8][CMAX];
    __shared__ float warp_loss[8];
    int w = threadIdx.x >> 5;
    int lane = threadIdx.x & 31;
    int n = blockIdx.x * 8 + w;

    if (lane == 0) s_cnt[w] = 0;
    __syncwarp();

    const uint4* rowp = (const uint4*)(g_dist + (size_t)n * KCODES);
    uint4 u[4];
    float vmin = 3.4e38f;
#pragma unroll
    for (int i = 0; i < 4; i++) {
        u[i] = rowp[lane + 32 * i];
        const uint32_t* ww = (const uint32_t*)&u[i];
#pragma unroll
        for (int j = 0; j < 4; j++) {
            float2 f = __half22float2(*(const __half2*)&ww[j]);
            vmin = fminf(vmin, fminf(f.x, f.y));
        }
    }
#pragma unroll
    for (int off = 16; off; off >>= 1)
        vmin = fminf(vmin, __shfl_xor_sync(0xFFFFFFFFu, vmin, off));
    float thr = vmin + MARGIN;

#pragma unroll
    for (int i = 0; i < 4; i++) {
        const uint32_t* ww = (const uint32_t*)&u[i];
#pragma unroll
        for (int j = 0; j < 4; j++) {
            float2 f = __half22float2(*(const __half2*)&ww[j]);
            int c0 = (lane + 32 * i) * 8 + j * 2;
            if (f.x <= thr) { int p = atomicAdd(&s_cnt[w], 1); if (p < CMAX) s_list[w][p] = c0; }
            if (f.y <= thr) { int p = atomicAdd(&s_cnt[w], 1); if (p < CMAX) s_list[w][p] = c0 + 1; }
        }
    }
    __syncwarp();
    int cnt = min(s_cnt[w], CMAX);

    const float4* zr = (const float4*)(z + (size_t)n * DIM);
    float4 za = zr[lane * 2], zb = zr[lane * 2 + 1];

    float bd = 3.4e38f;
    int bc = 0x7FFFFFFF;
    for (int t = 0; t < cnt; t++) {
        int c = s_list[w][t];
        const float4* er = (const float4*)(emb + (size_t)c * DIM);
        float4 ea = er[lane * 2], eb = er[lane * 2 + 1];
        float s = za.x*ea.x + za.y*ea.y + za.z*ea.z + za.w*ea.w
                + zb.x*eb.x + zb.y*eb.y + zb.z*eb.z + zb.w*eb.w;
#pragma unroll
        for (int off = 16; off; off >>= 1)
            s += __shfl_xor_sync(0xFFFFFFFFu, s, off);
        float d = g_enorm[c] - 2.0f * s;
        if (d < bd || (d == bd && c < bc)) { bd = d; bc = c; }
    }

    // fused gather + loss
    const float4* er = (const float4*)(emb + (size_t)bc * DIM);
    float4 ea = er[lane * 2], eb = er[lane * 2 + 1];
    float4* zq = (float4*)(out + OFF_ZQ + (size_t)n * DIM);
    zq[lane * 2]     = ea;
    zq[lane * 2 + 1] = eb;
    float lsum;
    {
        float dx = za.x-ea.x, dy = za.y-ea.y, dz = za.z-ea.z, dw = za.w-ea.w;
        lsum = dx*dx + dy*dy + dz*dz + dw*dw;
        dx = zb.x-eb.x; dy = zb.y-eb.y; dz = zb.z-eb.z; dw = zb.w-eb.w;
        lsum += dx*dx + dy*dy + dz*dz + dw*dw;
    }
#pragma unroll
    for (int off = 16; off; off >>= 1)
        lsum += __shfl_down_sync(0xFFFFFFFFu, lsum, off);
    if (lane == 0) {
        out[OFF_IDX + n] = (float)bc;
        g_sel[n] = bc;
        atomicAdd(&g_cnt[bc], 1);
        warp_loss[w] = lsum;
    }
    __syncthreads();
    if (threadIdx.x == 0) {
        float s = 0.0f;
#pragma unroll
        for (int i = 0; i < 8; i++) s += warp_loss[i];
        atomicAdd(&g_loss, s);
    }
}

// ---------------------------------------------------------------------------
// k_off: warp-shuffle exclusive scan of counts; write new_cluster_size
// ---------------------------------------------------------------------------
__global__ void k_off(const float* __restrict__ ema_cs, float* __restrict__ out) {
    __shared__ int sh[32];
    int t = threadIdx.x;
    int lane = t & 31, w = t >> 5;
    int v = g_cnt[t];
    out[OFF_CS + t] = DECAYF * ema_cs[t] + OMDECAY * (float)v;
    int incl = v;
#pragma unroll
    for (int off = 1; off < 32; off <<= 1) {
        int x = __shfl_up_sync(0xFFFFFFFFu, incl, off);
        if (lane >= off) incl += x;
    }
    if (lane == 31) sh[w] = incl;
    __syncthreads();
    if (w == 0) {
        int s = sh[lane];
        int inc = s;
#pragma unroll
        for (int off = 1; off < 32; off <<= 1) {
            int x = __shfl_up_sync(0xFFFFFFFFu, inc, off);
            if (lane >= off) inc += x;
        }
        sh[lane] = inc - s;   // exclusive warp offset
    }
    __syncthreads();
    g_off[t] = sh[w] + incl - v;
}

__global__ void k_fill() {
    int n = blockIdx.x * blockDim.x + threadIdx.x;
    int c = g_sel[n];
    int pos = g_off[c] + atomicAdd(&g_fill[c], 1);
    g_bkt[pos] = n;
}

__global__ __launch_bounds__(256) void k_dw(const float* __restrict__ z,
                                            const float* __restrict__ ema_w,
                                            float* __restrict__ out) {
    int c = blockIdx.x;
    int d = threadIdx.x;
    int beg = g_off[c], cnt = g_cnt[c];
    float acc = 0.0f;
    for (int m = 0; m < cnt; m++) {
        int p = g_bkt[beg + m];
        acc += z[(size_t)p * DIM + d];
    }
    out[OFF_EMAW + (size_t)c * DIM + d] =
        DECAYF * ema_w[(size_t)c * DIM + d] + OMDECAY * acc;
}

__global__ void k_nsum(const float* __restrict__ out) {
    __shared__ float sh[32];
    int t = threadIdx.x;
    float v = out[OFF_CS + t];
#pragma unroll
    for (int off = 16; off; off >>= 1) v += __shfl_down_sync(0xFFFFFFFFu, v, off);
    if ((t & 31) == 0) sh[t >> 5] = v;
    __syncthreads();
    if (t < 32) {
        float s = sh[t];
#pragma unroll
        for (int off = 16; off; off >>= 1) s += __shfl_down_sync(0xFFFFFFFFu, s, off);
        if (t == 0) g_n = s;
    }
}

__global__ void k_final(float* __restrict__ out) {
    int i = blockIdx.x * blockDim.x + threadIdx.x;
    float n = g_n;
    int k = i >> 8;
    float cs = (out[OFF_CS + k] + EPSF) / (n + (float)KCODES * EPSF) * n;
    out[OFF_EMB + i] = out[OFF_EMAW + i] / cs;
    if (i == 0)
        out[OFF_LOSS] = 1.25f * g_loss / (float)(N_PTS * DIM);
}

// ---------------------------------------------------------------------------
extern "C" void kernel_launch(void* const* d_in, const int* in_sizes, int n_in,
                              void* d_out, int out_size) {
    const float* z      = (const float*)d_in[0];
    const float* emb    = (const float*)d_in[1];
    const float* ema_cs = (const float*)d_in[2];
    const float* ema_w  = (const float*)d_in[3];
    float* out = (float*)d_out;

    cudaFuncSetAttribute(k_dist_imma,
                         cudaFuncAttributeMaxDynamicSharedMemorySize, SMEM_SZ);

    k_zero<<<1, 32>>>();
    k_maxabs<<<2048, 256>>>(z, emb);
    k_prep<<<(N_PTS * DIM / 4) / 256, 256>>>(z, emb);
    k_norm<<<(KCODES * 32) / 256, 256>>>(emb);
    k_dist_imma<<<dim3(KCODES / 128, N_PTS / 128), 256, SMEM_SZ>>>();
    k_selgather<<<N_PTS / 8, 256>>>(z, emb, out);
    k_off<<<1, KCODES>>>(ema_cs, out);
    k_fill<<<N_PTS / 256, 256>>>();
    k_dw<<<KCODES, 256>>>(z, ema_w, out);
    k_nsum<<<1, 1024>>>(out);
    k_final<<<(KCODES * DIM) / 256, 256>>>(out);
}

// round 16
// speedup vs baseline: 1.3478x; 1.3478x over previous
#include <cuda_runtime.h>
#include <cuda_fp16.h>
#include <cstdint>

#define N_PTS   32768
#define DIM     256
#define KCODES  1024
#define DECAYF  0.99f
#define OMDECAY 0.01f
#define EPSF    1e-5f
#define MARGIN  2.0f
#define CMAX    32

// Output layout (concatenated, float32)
#define OFF_ZQ    0
#define OFF_LOSS  (N_PTS * DIM)
#define OFF_IDX   (OFF_LOSS + 1)
#define OFF_EMB   (OFF_IDX + N_PTS)
#define OFF_CS    (OFF_EMB + KCODES * DIM)
#define OFF_EMAW  (OFF_CS + KCODES)

__device__ float  g_enorm[KCODES];
__device__ float  g_loss;
__device__ float  g_n;
__device__ __half g_zh[N_PTS * DIM];
__device__ __half g_eh[KCODES * DIM];
__device__ __half g_dist[N_PTS * KCODES];
__device__ int    g_sel[N_PTS];
__device__ int    g_cnt[KCODES];
__device__ int    g_off[KCODES];
__device__ int    g_fill[KCODES];
__device__ int    g_bkt[N_PTS];

// ---------------------------------------------------------------------------
// helpers
// ---------------------------------------------------------------------------
__device__ __forceinline__ uint32_t smem_u32(const void* p) {
    uint32_t a;
    asm("{ .reg .u64 t; cvta.to.shared.u64 t, %1; cvt.u32.u64 %0, t; }"
        : "=r"(a) : "l"(p));
    return a;
}
__device__ __forceinline__ void cp16(uint32_t dst, const void* src) {
    asm volatile("cp.async.cg.shared.global [%0], [%1], 16;"
                 :: "r"(dst), "l"(__cvta_generic_to_global(src)) : "memory");
}
#define CP_COMMIT() asm volatile("cp.async.commit_group;" ::: "memory")

#define LDSM_X4(r0, r1, r2, r3, a) \
    asm volatile("ldmatrix.sync.aligned.m8n8.x4.shared.b16 {%0,%1,%2,%3}, [%4];" \
                 : "=r"(r0), "=r"(r1), "=r"(r2), "=r"(r3) : "r"(a))
#define LDSM_X2(r0, r1, a) \
    asm volatile("ldmatrix.sync.aligned.m8n8.x2.shared.b16 {%0,%1}, [%2];" \
                 : "=r"(r0), "=r"(r1) : "r"(a))

__device__ __forceinline__ void mma16816(float* c, const uint32_t* a, const uint32_t* b) {
    asm volatile("mma.sync.aligned.m16n8k16.row.col.f32.f16.f16.f32 "
                 "{%0,%1,%2,%3}, {%4,%5,%6,%7}, {%8,%9}, {%0,%1,%2,%3};"
                 : "+f"(c[0]), "+f"(c[1]), "+f"(c[2]), "+f"(c[3])
                 : "r"(a[0]), "r"(a[1]), "r"(a[2]), "r"(a[3]), "r"(b[0]), "r"(b[1]));
}

// ---------------------------------------------------------------------------
// k_prep: fp32 -> fp16 (vectorized 4/thread); zero counters
// ---------------------------------------------------------------------------
__global__ void k_prep(const float* __restrict__ z, const float* __restrict__ e) {
    int idx = blockIdx.x * blockDim.x + threadIdx.x;     // covers N*D/4
    int i4 = idx * 4;
    float4 v = *(const float4*)(z + i4);
    __half2* zp = (__half2*)(g_zh + i4);
    zp[0] = __floats2half2_rn(v.x, v.y);
    zp[1] = __floats2half2_rn(v.z, v.w);
    if (i4 < KCODES * DIM) {
        float4 w = *(const float4*)(e + i4);
        __half2* ep = (__half2*)(g_eh + i4);
        ep[0] = __floats2half2_rn(w.x, w.y);
        ep[1] = __floats2half2_rn(w.z, w.w);
    }
    if (idx < KCODES) { g_cnt[idx] = 0; g_fill[idx] = 0; }
    if (idx == 0) g_loss = 0.0f;
}

__global__ void k_norm(const float* __restrict__ emb) {
    int warp = (blockIdx.x * blockDim.x + threadIdx.x) >> 5;
    int lane = threadIdx.x & 31;
    if (warp >= KCODES) return;
    const float4* row = (const float4*)(emb + (size_t)warp * DIM);
    float4 a = row[lane * 2 + 0];
    float4 b = row[lane * 2 + 1];
    float s = a.x*a.x + a.y*a.y + a.z*a.z + a.w*a.w
            + b.x*b.x + b.y*b.y + b.z*b.z + b.w*b.w;
#pragma unroll
    for (int off = 16; off; off >>= 1) s += __shfl_down_sync(0xFFFFFFFFu, s, off);
    if (lane == 0) g_enorm[warp] = s;
}

// ---------------------------------------------------------------------------
// HMMA fp16 distance GEMM (R9-proven config, unchanged):
// BM=128, BN=128, BK=64 halves, double-buffered cp.async, occupancy 2.
// ---------------------------------------------------------------------------
#define ROWB    144                      // 64 halves data + 8 pad = 144 bytes
#define EN_OFF  0
#define ST_A(s) (512 + (s) * 36864)
#define ST_B(s) (512 + (s) * 36864 + 18432)
#define SMEM_SZ (512 + 2 * 36864)        // 74240

__device__ __forceinline__ void load_stage(uint32_t sb, int s, int m0, int n0,
                                           int kk, int tid) {
#pragma unroll
    for (int i = 0; i < 4; i++) {
        int ch = tid + i * 256;          // 1024 chunks of 16B
        int r = ch >> 3, sg = ch & 7;
        uint32_t o = (uint32_t)(r * ROWB + sg * 16);
        cp16(sb + ST_A(s) + o, g_zh + (size_t)(m0 + r) * DIM + kk + sg * 8);
        cp16(sb + ST_B(s) + o, g_eh + (size_t)(n0 + r) * DIM + kk + sg * 8);
    }
}

__global__ __launch_bounds__(256, 2) void k_dist_hmma() {
    extern __shared__ char smem[];
    uint32_t sb = smem_u32(smem);
    int tid = threadIdx.x;
    int wid = tid >> 5;
    int lane = tid & 31;
    int n0 = blockIdx.x * 128;
    int m0 = blockIdx.y * 128;
    int warp_m = wid & 1;                // 2 tiles of 64 rows
    int warp_n = wid >> 1;               // 4 tiles of 32 cols

    if (tid < 128) ((float*)(smem + EN_OFF))[tid] = g_enorm[n0 + tid];

    float acc[4][4][4] = {};             // [mi 16][nj 8][frag]

    int rA = warp_m * 64 + (lane & 7) + (((lane >> 3) & 1) << 3);
    int cA8 = ((lane >> 4) & 1) << 3;
    int rB = warp_n * 32 + (lane & 7);
    int cB8 = ((lane >> 3) & 1) << 3;

    load_stage(sb, 0, m0, n0, 0, tid); CP_COMMIT();
    load_stage(sb, 1, m0, n0, 64, tid); CP_COMMIT();

    for (int c = 0; c < 4; c++) {
        int s = c & 1;
        if (c < 3) asm volatile("cp.async.wait_group 1;" ::: "memory");
        else       asm volatile("cp.async.wait_group 0;" ::: "memory");
        __syncthreads();

#pragma unroll
        for (int ks = 0; ks < 4; ks++) {
            int k0 = ks * 16;
            uint32_t a[4][4], b[4][2];
#pragma unroll
            for (int mi = 0; mi < 4; mi++) {
                uint32_t ad = sb + ST_A(s) + (rA + mi * 16) * ROWB + (k0 + cA8) * 2;
                LDSM_X4(a[mi][0], a[mi][1], a[mi][2], a[mi][3], ad);
            }
#pragma unroll
            for (int nj = 0; nj < 4; nj++) {
                uint32_t bd = sb + ST_B(s) + (rB + nj * 8) * ROWB + (k0 + cB8) * 2;
                LDSM_X2(b[nj][0], b[nj][1], bd);
            }
#pragma unroll
            for (int mi = 0; mi < 4; mi++)
#pragma unroll
                for (int nj = 0; nj < 4; nj++)
                    mma16816(acc[mi][nj], a[mi], b[nj]);
        }
        __syncthreads();
        if (c + 2 < 4) { load_stage(sb, s, m0, n0, (c + 2) * 64, tid); CP_COMMIT(); }
    }

    // epilogue: dist = en - 2*acc, store fp16
    const float* en = (const float*)(smem + EN_OFF);
#pragma unroll
    for (int mi = 0; mi < 4; mi++) {
#pragma unroll
        for (int nj = 0; nj < 4; nj++) {
            int cw = warp_n * 32 + nj * 8 + (lane & 3) * 2;
            int r0 = m0 + warp_m * 64 + mi * 16 + (lane >> 2);
            float e0 = en[cw], e1 = en[cw + 1];
            __half2 v0 = __floats2half2_rn(e0 - 2.0f * acc[mi][nj][0],
                                           e1 - 2.0f * acc[mi][nj][1]);
            __half2 v1 = __floats2half2_rn(e0 - 2.0f * acc[mi][nj][2],
                                           e1 - 2.0f * acc[mi][nj][3]);
            *(__half2*)(g_dist + (size_t)r0 * KCODES + n0 + cw) = v0;
            *(__half2*)(g_dist + (size_t)(r0 + 8) * KCODES + n0 + cw) = v1;
        }
    }
}

// ---------------------------------------------------------------------------
// k_selgather: warp per point. Full-row approx min -> margin candidates ->
// exact fp32 rescore -> fused gather (z_q, idx, loss, counts).
// ---------------------------------------------------------------------------
__global__ __launch_bounds__(256) void k_selgather(const float* __restrict__ z,
                                                   const float* __restrict__ emb,
                                                   float* __restrict__ out) {
    __shared__ int s_cnt[8];
    __shared__ int s_list[8][CMAX];
    __shared__ float warp_loss[8];
    int w = threadIdx.x >> 5;
    int lane = threadIdx.x & 31;
    int n = blockIdx.x * 8 + w;

    if (lane == 0) s_cnt[w] = 0;
    __syncwarp();

    const uint4* rowp = (const uint4*)(g_dist + (size_t)n * KCODES);
    uint4 u[4];
    float vmin = 3.4e38f;
#pragma unroll
    for (int i = 0; i < 4; i++) {
        u[i] = rowp[lane + 32 * i];
        const uint32_t* ww = (const uint32_t*)&u[i];
#pragma unroll
        for (int j = 0; j < 4; j++) {
            float2 f = __half22float2(*(const __half2*)&ww[j]);
            vmin = fminf(vmin, fminf(f.x, f.y));
        }
    }
#pragma unroll
    for (int off = 16; off; off >>= 1)
        vmin = fminf(vmin, __shfl_xor_sync(0xFFFFFFFFu, vmin, off));
    float thr = vmin + MARGIN;

#pragma unroll
    for (int i = 0; i < 4; i++) {
        const uint32_t* ww = (const uint32_t*)&u[i];
#pragma unroll
        for (int j = 0; j < 4; j++) {
            float2 f = __half22float2(*(const __half2*)&ww[j]);
            int c0 = (lane + 32 * i) * 8 + j * 2;
            if (f.x <= thr) { int p = atomicAdd(&s_cnt[w], 1); if (p < CMAX) s_list[w][p] = c0; }
            if (f.y <= thr) { int p = atomicAdd(&s_cnt[w], 1); if (p < CMAX) s_list[w][p] = c0 + 1; }
        }
    }
    __syncwarp();
    int cnt = min(s_cnt[w], CMAX);

    const float4* zr = (const float4*)(z + (size_t)n * DIM);
    float4 za = zr[lane * 2], zb = zr[lane * 2 + 1];

    float bd = 3.4e38f;
    int bc = 0x7FFFFFFF;
    for (int t = 0; t < cnt; t++) {
        int c = s_list[w][t];
        const float4* er = (const float4*)(emb + (size_t)c * DIM);
        float4 ea = er[lane * 2], eb = er[lane * 2 + 1];
        float s = za.x*ea.x + za.y*ea.y + za.z*ea.z + za.w*ea.w
                + zb.x*eb.x + zb.y*eb.y + zb.z*eb.z + zb.w*eb.w;
#pragma unroll
        for (int off = 16; off; off >>= 1)
            s += __shfl_xor_sync(0xFFFFFFFFu, s, off);
        float d = g_enorm[c] - 2.0f * s;
        if (d < bd || (d == bd && c < bc)) { bd = d; bc = c; }
    }

    // fused gather + loss
    const float4* er = (const float4*)(emb + (size_t)bc * DIM);
    float4 ea = er[lane * 2], eb = er[lane * 2 + 1];
    float4* zq = (float4*)(out + OFF_ZQ + (size_t)n * DIM);
    zq[lane * 2]     = ea;
    zq[lane * 2 + 1] = eb;
    float lsum;
    {
        float dx = za.x-ea.x, dy = za.y-ea.y, dz = za.z-ea.z, dw = za.w-ea.w;
        lsum = dx*dx + dy*dy + dz*dz + dw*dw;
        dx = zb.x-eb.x; dy = zb.y-eb.y; dz = zb.z-eb.z; dw = zb.w-eb.w;
        lsum += dx*dx + dy*dy + dz*dz + dw*dw;
    }
#pragma unroll
    for (int off = 16; off; off >>= 1)
        lsum += __shfl_down_sync(0xFFFFFFFFu, lsum, off);
    if (lane == 0) {
        out[OFF_IDX + n] = (float)bc;
        g_sel[n] = bc;
        atomicAdd(&g_cnt[bc], 1);
        warp_loss[w] = lsum;
    }
    __syncthreads();
    if (threadIdx.x == 0) {
        float s = 0.0f;
#pragma unroll
        for (int i = 0; i < 8; i++) s += warp_loss[i];
        atomicAdd(&g_loss, s);
    }
}

// ---------------------------------------------------------------------------
// k_off: warp-shuffle exclusive scan of counts; new_cluster_size; fused n-sum
// ---------------------------------------------------------------------------
__global__ void k_off(const float* __restrict__ ema_cs, float* __restrict__ out) {
    __shared__ int   sh[32];
    __shared__ float fs[32];
    int t = threadIdx.x;
    int lane = t & 31, w = t >> 5;
    int v = g_cnt[t];
    float cs = DECAYF * ema_cs[t] + OMDECAY * (float)v;
    out[OFF_CS + t] = cs;

    // exclusive scan of counts -> g_off
    int incl = v;
#pragma unroll
    for (int off = 1; off < 32; off <<= 1) {
        int x = __shfl_up_sync(0xFFFFFFFFu, incl, off);
        if (lane >= off) incl += x;
    }
    if (lane == 31) sh[w] = incl;

    // block sum of cs -> g_n
    float r = cs;
#pragma unroll
    for (int off = 16; off; off >>= 1) r += __shfl_down_sync(0xFFFFFFFFu, r, off);
    if (lane == 0) fs[w] = r;

    __syncthreads();
    if (w == 0) {
        int s = sh[lane];
        int inc = s;
#pragma unroll
        for (int off = 1; off < 32; off <<= 1) {
            int x = __shfl_up_sync(0xFFFFFFFFu, inc, off);
            if (lane >= off) inc += x;
        }
        sh[lane] = inc - s;   // exclusive warp offset

        float fsum = fs[lane];
#pragma unroll
        for (int off = 16; off; off >>= 1)
            fsum += __shfl_down_sync(0xFFFFFFFFu, fsum, off);
        if (lane == 0) g_n = fsum;
    }
    __syncthreads();
    g_off[t] = sh[w] + incl - v;
}

__global__ void k_fill() {
    int n = blockIdx.x * blockDim.x + threadIdx.x;
    int c = g_sel[n];
    int pos = g_off[c] + atomicAdd(&g_fill[c], 1);
    g_bkt[pos] = n;
}

__global__ __launch_bounds__(256) void k_dw(const float* __restrict__ z,
                                            const float* __restrict__ ema_w,
                                            float* __restrict__ out) {
    int c = blockIdx.x;
    int d = threadIdx.x;
    int beg = g_off[c], cnt = g_cnt[c];
    float acc = 0.0f;
    for (int m = 0; m < cnt; m++) {
        int p = g_bkt[beg + m];
        acc += z[(size_t)p * DIM + d];
    }
    out[OFF_EMAW + (size_t)c * DIM + d] =
        DECAYF * ema_w[(size_t)c * DIM + d] + OMDECAY * acc;
}

__global__ void k_final(float* __restrict__ out) {
    int i = blockIdx.x * blockDim.x + threadIdx.x;
    float n = g_n;
    int k = i >> 8;
    float cs = (out[OFF_CS + k] + EPSF) / (n + (float)KCODES * EPSF) * n;
    out[OFF_EMB + i] = out[OFF_EMAW + i] / cs;
    if (i == 0)
        out[OFF_LOSS] = 1.25f * g_loss / (float)(N_PTS * DIM);
}

// ---------------------------------------------------------------------------
extern "C" void kernel_launch(void* const* d_in, const int* in_sizes, int n_in,
                              void* d_out, int out_size) {
    const float* z      = (const float*)d_in[0];
    const float* emb    = (const float*)d_in[1];
    const float* ema_cs = (const float*)d_in[2];
    const float* ema_w  = (const float*)d_in[3];
    float* out = (float*)d_out;

    cudaFuncSetAttribute(k_dist_hmma,
                         cudaFuncAttributeMaxDynamicSharedMemorySize, SMEM_SZ);

    k_prep<<<(N_PTS * DIM / 4) / 256, 256>>>(z, emb);
    k_norm<<<(KCODES * 32) / 256, 256>>>(emb);
    k_dist_hmma<<<dim3(KCODES / 128, N_PTS / 128), 256, SMEM_SZ>>>();
    k_selgather<<<N_PTS / 8, 256>>>(z, emb, out);
    k_off<<<1, KCODES>>>(ema_cs, out);
    k_fill<<<N_PTS / 256, 256>>>();
    k_dw<<<KCODES, 256>>>(z, ema_w, out);
    k_final<<<(KCODES * DIM) / 256, 256>>>(out);
}